// round 6
// baseline (speedup 1.0000x reference)
#include <cuda_runtime.h>

// PINO elasticity loss on the fixed structured G x G grid mesh.
// Exploits: all triangles congruent, B entries in {0, +-1/h}, area = h^2/2,
// total_area = 1. R is a constant 7-point 2x2-block stencil (interior),
// boundary nodes use the masked per-triangle path. Single fused kernel with
// last-block finalize (graph-replay safe: last block resets the accumulators).

#define G 1024
#define NG (G * G)
#define NBLK 4096  // (G/32) * (G/8)

__device__ double g_acc[2];        // [0] sum of unscaled (Rx^2+Ry^2), [1] sum of unscaled energy
__device__ unsigned int g_count;   // finished-block counter (reset by last block)

__global__ __launch_bounds__(256) void k_main(const float2* __restrict__ up,
                                              const float2* __restrict__ ut,
                                              float* __restrict__ out) {
    const float NU = 0.3f;   // Poisson
    const float SH = 0.35f;  // (1-nu)/2
    const float TN = 0.6f;   // 2*nu

    // 32(j) x 8(i) tile per block: vertical neighbors hit L1 within the tile.
    int tj = threadIdx.x & 31;
    int ti = threadIdx.x >> 5;
    int j = (blockIdx.x << 5) + tj;
    int i = (blockIdx.y << 3) + ti;
    int idx = (i << 10) + j;

    bool bi0 = (i > 0), bi1 = (i < G - 1), bj0 = (j > 0), bj1 = (j < G - 1);

    // Clamped neighbor offsets: loads stay in-bounds; out-of-range values are
    // garbage-but-valid and only consumed under the proper masks.
    int jm = bj0 ? -1 : 0;
    int jp = bj1 ? 1 : 0;
    int im = bi0 ? -G : 0;
    int ip = bi1 ? G : 0;

    float2 u0 = up[idx];
    float2 ue = up[idx + jp];        // (i, j+1)
    float2 uw = up[idx + jm];        // (i, j-1)
    float2 un = up[idx + ip];        // (i+1, j)
    float2 us = up[idx + im];        // (i-1, j)
    float2 uP = up[idx + ip + jm];   // (i+1, j-1)
    float2 uQ = up[idx + im + jp];   // (i-1, j+1)

    float eq;
    float en = 0.0f;

    if (bi0 & bi1 & bj0 & bj1) {
        // Assembled interior stencil (unscaled; true R = (0.5/0.91) * this).
        float sxns = un.x + us.x, syns = un.y + us.y;
        float sxew = ue.x + uw.x, syew = ue.y + uw.y;
        float spqx = uP.x + uQ.x, spqy = uP.y + uQ.y;
        float Rx = 5.4f * u0.x + 1.3f * u0.y
                 - 2.0f  * sxns - 0.65f * syns
                 - 0.7f  * sxew - 0.65f * syew
                 + 0.65f * spqy;
        float Ry = 1.3f * u0.x + 5.4f * u0.y
                 - 0.65f * sxns - 0.7f  * syns
                 - 0.65f * sxew - 2.0f  * syew
                 + 0.65f * spqx;
        eq = Rx * Rx + Ry * Ry;
    } else {
        // Boundary: masked sum over the up-to-6 incident triangles.
        float Rx = 0.0f, Ry = 0.0f;
        float e0, e1, e2, s0, s1, s2;
        // T1: tri1(i,j)   a=u0, b=ue, c=un           valid: i1 && j1
        if (bi1 && bj1) {
            e0 = un.x - u0.x; e1 = ue.y - u0.y; e2 = (ue.x - u0.x) + (un.y - u0.y);
            s0 = e0 + NU * e1; s1 = NU * e0 + e1; s2 = SH * e2;
            Rx -= s0 + s2; Ry -= s1 + s2;
        }
        // T2: tri1(i,j-1) a=uw, b=u0, c=uP           valid: i1 && j0
        if (bi1 && bj0) {
            e0 = uP.x - uw.x; e1 = u0.y - uw.y; e2 = (u0.x - uw.x) + (uP.y - uw.y);
            Rx += SH * e2; Ry += NU * e0 + e1;
        }
        // T3: tri1(i-1,j) a=us, b=uQ, c=u0           valid: i0 && j1
        if (bi0 && bj1) {
            e0 = u0.x - us.x; e1 = uQ.y - us.y; e2 = (uQ.x - us.x) + (u0.y - us.y);
            Rx += e0 + NU * e1; Ry += SH * e2;
        }
        // T4: tri2(i,j-1) b=u0, d=un, c=uP           valid: i1 && j0
        if (bi1 && bj0) {
            e0 = un.x - u0.x; e1 = un.y - uP.y; e2 = -u0.y + un.x + un.y - uP.x;
            Rx -= e0 + NU * e1; Ry -= SH * e2;
        }
        // T5: tri2(i-1,j-1) b=us, d=u0, c=uw         valid: i0 && j0
        if (bi0 && bj0) {
            e0 = u0.x - us.x; e1 = u0.y - uw.y; e2 = -us.y + u0.x + u0.y - uw.x;
            s0 = e0 + NU * e1; s1 = NU * e0 + e1; s2 = SH * e2;
            Rx += s0 + s2; Ry += s1 + s2;
        }
        // T6: tri2(i-1,j) b=uQ, d=ue, c=u0           valid: i0 && j1
        if (bi0 && bj1) {
            e0 = ue.x - uQ.x; e1 = ue.y - u0.y; e2 = -uQ.y + ue.x + ue.y - u0.x;
            Rx -= SH * e2; Ry -= NU * e0 + e1;
        }
        eq = Rx * Rx + Ry * Ry;
    }

    // Energy for cell (i,j): triangles of the cell with corners
    // a=(i,j), b=(i,j+1), c=(i+1,j), d=(i+1,j+1), on u_err = u_pred - u_true.
    if (bi1 && bj1) {
        float2 une = up[idx + G + 1];
        float2 t0 = ut[idx];
        float2 te = ut[idx + 1];
        float2 tn = ut[idx + G];
        float2 tq = ut[idx + G + 1];
        float ax = u0.x - t0.x, ay = u0.y - t0.y;
        float bx = ue.x - te.x, by = ue.y - te.y;
        float cx = un.x - tn.x, cy = un.y - tn.y;
        float dx = une.x - tq.x, dy = une.y - tq.y;
        // tri1
        float e0 = cx - ax;
        float e1 = by - ay;
        float e2 = (bx - ax) + (cy - ay);
        en = e0 * e0 + e1 * e1 + TN * e0 * e1 + SH * e2 * e2;
        // tri2
        e0 = dx - bx;
        e1 = dy - cy;
        e2 = -by + dx + dy - cx;
        en += e0 * e0 + e1 * e1 + TN * e0 * e1 + SH * e2 * e2;
    }

    // Block reduction (8 warps), then double atomics.
    #pragma unroll
    for (int o = 16; o > 0; o >>= 1) {
        eq += __shfl_xor_sync(0xFFFFFFFFu, eq, o);
        en += __shfl_xor_sync(0xFFFFFFFFu, en, o);
    }
    __shared__ float s_eq[8], s_en[8];
    int w = threadIdx.x >> 5, l = threadIdx.x & 31;
    if (l == 0) { s_eq[w] = eq; s_en[w] = en; }
    __syncthreads();
    if (threadIdx.x == 0) {
        float teq = 0.0f, ten = 0.0f;
        #pragma unroll
        for (int k = 0; k < 8; k++) { teq += s_eq[k]; ten += s_en[k]; }
        atomicAdd(&g_acc[0], (double)teq);
        atomicAdd(&g_acc[1], (double)ten);
        __threadfence();
        unsigned int done = atomicAdd(&g_count, 1u);
        if (done == NBLK - 1) {
            // Last block: finalize and reset for the next graph replay.
            const double K = 0.5 / 0.91;               // 0.5 * 1/(1-nu^2)
            double L_eq = (K * K) * g_acc[0] / (2.0 * (double)NG);
            double L_en = K * g_acc[1];                // total_area == 1 exactly
            out[0] = (float)(0.1 * L_eq + 0.1 * L_en);
            g_acc[0] = 0.0;
            g_acc[1] = 0.0;
            g_count = 0u;
        }
    }
}

extern "C" void kernel_launch(void* const* d_in, const int* in_sizes, int n_in,
                              void* d_out, int out_size) {
    const float2* up = (const float2*)d_in[0];
    const float2* ut = (const float2*)d_in[1];
    float* out = (float*)d_out;
    (void)in_sizes; (void)n_in; (void)out_size;

    dim3 grid(G / 32, G / 8);
    k_main<<<grid, 256>>>(up, ut, out);
}

// round 7
// speedup vs baseline: 1.6923x; 1.6923x over previous
#include <cuda_runtime.h>

// PINO elasticity loss on the fixed structured G x G grid mesh.
// R is a constant 7-point 2x2-block stencil (interior); boundary nodes use the
// masked per-triangle path. 4 nodes per thread (i-column), all loads preloaded
// for MLP; single kernel with last-block finalize.

#define G 1024
#define NG (G * G)
#define NBLK 1024  // (G/32) * (G/32); each block covers a 32x32 node tile

__device__ double g_acc[2];        // [0] sum of unscaled (Rx^2+Ry^2), [1] sum of unscaled energy
__device__ unsigned int g_count;   // finished-block counter (reset by last block)

__global__ __launch_bounds__(256) void k_main(const float2* __restrict__ up,
                                              const float2* __restrict__ ut,
                                              float* __restrict__ out) {
    const float NU = 0.3f;   // Poisson
    const float SH = 0.35f;  // (1-nu)/2
    const float TN = 0.6f;   // 2*nu

    // Block tile: 32 (j) x 32 (i); thread = one j, four consecutive i.
    int tj = threadIdx.x & 31;
    int ti = threadIdx.x >> 5;
    int j  = (blockIdx.x << 5) + tj;
    int i0 = (blockIdx.y << 5) + (ti << 2);

    bool bj0 = (j > 0), bj1 = (j < G - 1);
    int jm = bj0 ? -1 : 0;
    int jp = bj1 ? 1 : 0;

    // Preload 6 up rows (i0-1 .. i0+4) x 3 columns (j-1, j, j+1), row-clamped.
    // Clamped rows are garbage-but-valid and only consumed under masks.
    float2 W[6], C[6], E[6];
    #pragma unroll
    for (int r = 0; r < 6; r++) {
        int ri = i0 - 1 + r;
        ri = ri < 0 ? 0 : (ri > G - 1 ? G - 1 : ri);
        int base = (ri << 10) + j;
        W[r] = up[base + jm];
        C[r] = up[base];
        E[r] = up[base + jp];
    }
    // Preload 5 ut rows (i0 .. i0+4) x 2 columns (j, j+1), row-clamped.
    float2 TC[5], TD[5];
    #pragma unroll
    for (int r = 0; r < 5; r++) {
        int ri = i0 + r;
        ri = ri > G - 1 ? G - 1 : ri;
        int base = (ri << 10) + j;
        TC[r] = ut[base];
        TD[r] = ut[base + jp];
    }

    float eq = 0.0f, en = 0.0f;

    #pragma unroll
    for (int k = 0; k < 4; k++) {
        int i = i0 + k;
        bool bi0 = (i > 0), bi1 = (i < G - 1);

        float2 us = C[k],     u0 = C[k + 1], un = C[k + 2];
        float2 uw = W[k + 1], ue = E[k + 1];
        float2 uP = W[k + 2];   // (i+1, j-1)
        float2 uQ = E[k];       // (i-1, j+1)

        if (bi0 & bi1 & bj0 & bj1) {
            // Assembled interior stencil (unscaled; true R = (0.5/0.91) * this).
            float sxns = un.x + us.x, syns = un.y + us.y;
            float sxew = ue.x + uw.x, syew = ue.y + uw.y;
            float spqx = uP.x + uQ.x, spqy = uP.y + uQ.y;
            float Rx = 5.4f * u0.x + 1.3f * u0.y
                     - 2.0f  * sxns - 0.65f * syns
                     - 0.7f  * sxew - 0.65f * syew
                     + 0.65f * spqy;
            float Ry = 1.3f * u0.x + 5.4f * u0.y
                     - 0.65f * sxns - 0.7f  * syns
                     - 0.65f * sxew - 2.0f  * syew
                     + 0.65f * spqx;
            eq += Rx * Rx + Ry * Ry;
        } else {
            // Boundary: masked sum over the up-to-6 incident triangles.
            float Rx = 0.0f, Ry = 0.0f;
            float e0, e1, e2, s0, s1, s2;
            if (bi1 && bj1) {  // T1: tri1(i,j)   a=u0, b=ue, c=un
                e0 = un.x - u0.x; e1 = ue.y - u0.y; e2 = (ue.x - u0.x) + (un.y - u0.y);
                s0 = e0 + NU * e1; s1 = NU * e0 + e1; s2 = SH * e2;
                Rx -= s0 + s2; Ry -= s1 + s2;
            }
            if (bi1 && bj0) {  // T2: tri1(i,j-1) a=uw, b=u0, c=uP
                e0 = uP.x - uw.x; e1 = u0.y - uw.y; e2 = (u0.x - uw.x) + (uP.y - uw.y);
                Rx += SH * e2; Ry += NU * e0 + e1;
            }
            if (bi0 && bj1) {  // T3: tri1(i-1,j) a=us, b=uQ, c=u0
                e0 = u0.x - us.x; e1 = uQ.y - us.y; e2 = (uQ.x - us.x) + (u0.y - us.y);
                Rx += e0 + NU * e1; Ry += SH * e2;
            }
            if (bi1 && bj0) {  // T4: tri2(i,j-1) b=u0, d=un, c=uP
                e0 = un.x - u0.x; e1 = un.y - uP.y; e2 = -u0.y + un.x + un.y - uP.x;
                Rx -= e0 + NU * e1; Ry -= SH * e2;
            }
            if (bi0 && bj0) {  // T5: tri2(i-1,j-1) b=us, d=u0, c=uw
                e0 = u0.x - us.x; e1 = u0.y - uw.y; e2 = -us.y + u0.x + u0.y - uw.x;
                s0 = e0 + NU * e1; s1 = NU * e0 + e1; s2 = SH * e2;
                Rx += s0 + s2; Ry += s1 + s2;
            }
            if (bi0 && bj1) {  // T6: tri2(i-1,j) b=uQ, d=ue, c=u0
                e0 = ue.x - uQ.x; e1 = ue.y - u0.y; e2 = -uQ.y + ue.x + ue.y - u0.x;
                Rx -= SH * e2; Ry -= NU * e0 + e1;
            }
            eq += Rx * Rx + Ry * Ry;
        }

        // Energy for cell (i,j): corners a=(i,j), b=(i,j+1), c=(i+1,j),
        // d=(i+1,j+1) on u_err = u_pred - u_true.
        if (bi1 && bj1) {
            float2 une = E[k + 2];
            float2 t0 = TC[k], te = TD[k], tn = TC[k + 1], tq = TD[k + 1];
            float ax = u0.x - t0.x,  ay = u0.y - t0.y;
            float bx = ue.x - te.x,  by = ue.y - te.y;
            float cx = un.x - tn.x,  cy = un.y - tn.y;
            float dx = une.x - tq.x, dy = une.y - tq.y;
            float e0 = cx - ax;
            float e1 = by - ay;
            float e2 = (bx - ax) + (cy - ay);
            en += e0 * e0 + e1 * e1 + TN * e0 * e1 + SH * e2 * e2;
            e0 = dx - bx;
            e1 = dy - cy;
            e2 = -by + dx + dy - cx;
            en += e0 * e0 + e1 * e1 + TN * e0 * e1 + SH * e2 * e2;
        }
    }

    // Block reduction (8 warps), then one double-atomic pair per block.
    #pragma unroll
    for (int o = 16; o > 0; o >>= 1) {
        eq += __shfl_xor_sync(0xFFFFFFFFu, eq, o);
        en += __shfl_xor_sync(0xFFFFFFFFu, en, o);
    }
    __shared__ float s_eq[8], s_en[8];
    int w = threadIdx.x >> 5, l = threadIdx.x & 31;
    if (l == 0) { s_eq[w] = eq; s_en[w] = en; }
    __syncthreads();
    if (threadIdx.x == 0) {
        float teq = 0.0f, ten = 0.0f;
        #pragma unroll
        for (int r = 0; r < 8; r++) { teq += s_eq[r]; ten += s_en[r]; }
        atomicAdd(&g_acc[0], (double)teq);
        atomicAdd(&g_acc[1], (double)ten);
        __threadfence();
        unsigned int done = atomicAdd(&g_count, 1u);
        if (done == NBLK - 1) {
            // Last block: finalize and reset for the next graph replay.
            const double K = 0.5 / 0.91;               // 0.5 * 1/(1-nu^2)
            double L_eq = (K * K) * g_acc[0] / (2.0 * (double)NG);
            double L_en = K * g_acc[1];                // total_area == 1 exactly
            out[0] = (float)(0.1 * L_eq + 0.1 * L_en);
            g_acc[0] = 0.0;
            g_acc[1] = 0.0;
            g_count = 0u;
        }
    }
}

extern "C" void kernel_launch(void* const* d_in, const int* in_sizes, int n_in,
                              void* d_out, int out_size) {
    const float2* up = (const float2*)d_in[0];
    const float2* ut = (const float2*)d_in[1];
    float* out = (float*)d_out;
    (void)in_sizes; (void)n_in; (void)out_size;

    dim3 grid(G / 32, G / 32);
    k_main<<<grid, 256>>>(up, ut, out);
}